// round 5
// baseline (speedup 1.0000x reference)
#include <cuda_runtime.h>

#define TPB     256
#define NBLOCKS 1216     // 152 SMs * 8 resident blocks (regs<=32): one wave
#define MACRO   (TPB * 4)

// ---------------------------------------------------------------------------
// out = sum_i x[i]*c[i] + sum_g c2[g] * x[i(g)] * x[j(g)]
// where g is the FLAT index into the packed upper triangle (row-major),
// i(g) = row containing g, j(g) = g - base(i) + i + 1, base(i)=i*(2n-1-i)/2.
//
// Each block streams a CONTIGUOUS, aligned chunk of c2 (ideal DRAM pattern:
// coalesced 128B warp loads, every line touched once, one sequential stream
// per block). Row bookkeeping is a per-thread incremental (i, rb, re) state
// advanced by a rarely-taken while as g strides by TPB. All x reads are
// coalesced L1 hits.
// ---------------------------------------------------------------------------

__global__ void zero_out_kernel(float* out) {
    if (threadIdx.x == 0 && blockIdx.x == 0) out[0] = 0.0f;
}

__device__ __forceinline__ float warp_sum(float v) {
    #pragma unroll
    for (int o = 16; o > 0; o >>= 1) v += __shfl_down_sync(0xffffffffu, v, o);
    return v;
}

// advance row state so that rb <= g < re, row i; updates xi and joff
#define ADVANCE(gv)                                                     \
    while ((gv) >= re) {                                                \
        rb = re; ++i; re += (n - 1 - i);                                \
        xi = __ldg(x + i); joff = i + 1 - rb;                           \
    }

__global__ __launch_bounds__(TPB, 8)
void ham_kernel(const float* __restrict__ x,
                const float* __restrict__ c,
                float* __restrict__ out,
                int n) {
    const int t   = threadIdx.x;
    const int bid = blockIdx.x;
    const float* c2 = c + n;

    const int total = (n * (n - 1)) >> 1;          // 33,550,336 (fits int)
    const int nmac  = total / MACRO;               // 32,764 for n=8192
    const int tail0 = nmac * MACRO;

    // contiguous macro-chunk per block
    const int per = nmac / gridDim.x;
    const int rem = nmac - per * gridDim.x;
    const int m0  = bid * per + (bid < rem ? bid : rem);
    const int m1  = m0 + per + (bid < rem ? 1 : 0);
    const int e0  = m0 * MACRO;
    const int e1  = m1 * MACRO;

    float acc = 0.0f;

    // degree-1 terms, spread over all blocks
    for (int k = bid * TPB + t; k < n; k += gridDim.x * TPB)
        acc += __ldg(x + k) * __ldg(c + k);

    if (e0 < e1) {
        // --- decode starting row for g = e0 + t (double seed + exact fixup)
        int g = e0 + t;
        const double nd = 2.0 * (double)n - 1.0;
        int i = (int)((nd - sqrt(nd * nd - 8.0 * (double)g)) * 0.5);
        if (i < 0) i = 0;
        if (i > n - 2) i = n - 2;
        int rb = (i * (2 * n - 1 - i)) >> 1;
        while (rb > g) { --i; rb -= (n - 1 - i); }
        int re = rb + (n - 1 - i);
        while (g >= re) { rb = re; ++i; re += (n - 1 - i); }
        float xi  = __ldg(x + i);
        int  joff = i + 1 - rb;

        // --- main stream: block-contiguous, warp-coalesced, aligned
        for (int gb = e0; gb < e1; gb += MACRO) {
            const int g0 = gb + t;
            // 4 independent streaming loads in flight (addresses are pure g)
            const float k0 = __ldcs(c2 + g0);
            const float k1 = __ldcs(c2 + g0 + TPB);
            const float k2 = __ldcs(c2 + g0 + 2 * TPB);
            const float k3 = __ldcs(c2 + g0 + 3 * TPB);

            ADVANCE(g0);
            acc = fmaf(k0, xi * __ldg(x + g0 + joff), acc);
            const int g1 = g0 + TPB;
            ADVANCE(g1);
            acc = fmaf(k1, xi * __ldg(x + g1 + joff), acc);
            const int g2 = g1 + TPB;
            ADVANCE(g2);
            acc = fmaf(k2, xi * __ldg(x + g2 + joff), acc);
            const int g3 = g2 + TPB;
            ADVANCE(g3);
            acc = fmaf(k3, xi * __ldg(x + g3 + joff), acc);
        }
    }

    // remainder elements (total % MACRO; 0 for n=8192 but keep it correct)
    for (int g = tail0 + bid * TPB + t; g < total; g += gridDim.x * TPB) {
        const double nd = 2.0 * (double)n - 1.0;
        int i = (int)((nd - sqrt(nd * nd - 8.0 * (double)g)) * 0.5);
        if (i < 0) i = 0;
        if (i > n - 2) i = n - 2;
        int rb = (i * (2 * n - 1 - i)) >> 1;
        while (rb > g) { --i; rb -= (n - 1 - i); }
        while (g >= rb + (n - 1 - i)) { rb += (n - 1 - i); ++i; }
        const int j = g - rb + i + 1;
        acc = fmaf(__ldcs(c2 + g), __ldg(x + i) * __ldg(x + j), acc);
    }

    // block reduction: warp shuffle -> smem -> warp 0 -> one atomic per block
    __shared__ float wsum[TPB / 32];
    float w = warp_sum(acc);
    if ((t & 31) == 0) wsum[t >> 5] = w;
    __syncthreads();
    if (t < 32) {
        float v = (t < TPB / 32) ? wsum[t] : 0.0f;
        v = warp_sum(v);
        if (t == 0) atomicAdd(out, v);
    }
}

extern "C" void kernel_launch(void* const* d_in, const int* in_sizes, int n_in,
                              void* d_out, int out_size) {
    const float* x = (const float*)d_in[0];
    const float* c = (const float*)d_in[1];
    float* out = (float*)d_out;
    const int n = in_sizes[0];   // 8192

    zero_out_kernel<<<1, 32>>>(out);
    ham_kernel<<<NBLOCKS, TPB>>>(x, c, out, n);
}

// round 6
// speedup vs baseline: 1.6619x; 1.6619x over previous
#include <cuda_runtime.h>

#define TPB     256
#define NBLOCKS 1216     // 152 SMs * 8 resident blocks (regs=32): one wave
#define W       512      // column-strip width (= 2 * TPB)

// ---------------------------------------------------------------------------
// out = sum_j x[j] * ( c1[j] + sum_{i<j} x[i] * c2[base(i) + (j-i-1)] )
// c2 = c + n, base(i) = i*(2n-1-i)/2  (row-major packed upper triangle).
//
// Work unit = one ROW-SEGMENT: row i restricted to column strip js
// (columns [js*W, js*W+W)). Strip js contains K_js = (js+1)*W - 1 rows
// (i < max j). Units are globally ordered (strip-major, then row); block b
// owns the contiguous range [b*U/G, (b+1)*U/G)  ->  <=1 row imbalance.
//
// Thread t owns columns j_a = js*W + t, j_b = j_a + TPB with one register
// accumulator each; inner loop reads ONLY the coeff stream (coalesced,
// evict-first) + one uniform x[i] per row. Fold by x[j] once per strip.
// ---------------------------------------------------------------------------

__global__ void zero_out_kernel(float* out) {
    if (threadIdx.x == 0 && blockIdx.x == 0) out[0] = 0.0f;
}

__device__ __forceinline__ float warp_sum(float v) {
    #pragma unroll
    for (int o = 16; o > 0; o >>= 1) v += __shfl_down_sync(0xffffffffu, v, o);
    return v;
}

__global__ __launch_bounds__(TPB, 8)
void ham_kernel(const float* __restrict__ x,
                const float* __restrict__ c,
                float* __restrict__ out,
                int n) {
    const int t   = threadIdx.x;
    const int b   = blockIdx.x;
    const int G   = gridDim.x;
    const float* c2 = c + n;

    const int ns = n / W;                       // 16 strips
    const int U  = W * (ns * (ns + 1) / 2) - ns; // 69616 row-segments total

    const int u0 = (int)(((long long)b       * U) / G);
    const int u1 = (int)(((long long)(b + 1) * U) / G);

    float sum = 0.0f;

    // degree-1 terms, spread over all blocks
    for (int k = b * TPB + t; k < n; k += G * TPB)
        sum += __ldg(x + k) * __ldg(c + k);

    // locate starting strip for unit u0
    int js = 0, Pjs = 0;
    while (Pjs + ((js + 1) * W - 1) <= u0) { Pjs += (js + 1) * W - 1; ++js; }
    int i = u0 - Pjs;                // starting row within strip js
    int u = u0;

    while (u < u1) {
        const int K   = (js + 1) * W - 1;       // rows in this strip
        const int j0  = js * W;
        const int j_a = j0 + t;
        const int j_b = j_a + TPB;

        int iend = i + (u1 - u);
        if (iend > K) iend = K;
        const int iclean = (iend < j0) ? iend : j0;

        float acc0 = 0.0f, acc1 = 0.0f;
        const float* p = c2 + ((i * (2 * n - 1 - i)) >> 1) + (j_a - i - 1);

        // ---- clean rows (whole row strictly above diagonal), unroll 4 ----
        for (; i + 4 <= iclean; ) {
            const int o1 = n - 2 - i;
            const int o2 = 2 * n - 5 - 2 * i;
            const int o3 = 3 * n - 9 - 3 * i;
            const float xi0 = __ldg(x + i);
            const float xi1 = __ldg(x + i + 1);
            const float xi2 = __ldg(x + i + 2);
            const float xi3 = __ldg(x + i + 3);
            // 8 independent streaming loads in flight
            const float a0 = __ldcs(p);
            const float b0 = __ldcs(p + TPB);
            const float a1 = __ldcs(p + o1);
            const float b1 = __ldcs(p + o1 + TPB);
            const float a2 = __ldcs(p + o2);
            const float b2 = __ldcs(p + o2 + TPB);
            const float a3 = __ldcs(p + o3);
            const float b3 = __ldcs(p + o3 + TPB);
            acc0 = fmaf(xi0, a0, acc0);  acc1 = fmaf(xi0, b0, acc1);
            acc0 = fmaf(xi1, a1, acc0);  acc1 = fmaf(xi1, b1, acc1);
            acc0 = fmaf(xi2, a2, acc0);  acc1 = fmaf(xi2, b2, acc1);
            acc0 = fmaf(xi3, a3, acc0);  acc1 = fmaf(xi3, b3, acc1);
            p += 4 * n - 14 - 4 * i;
            i += 4;
        }
        for (; i < iclean; ++i) {
            const float xi = __ldg(x + i);
            acc0 = fmaf(xi, __ldcs(p), acc0);
            acc1 = fmaf(xi, __ldcs(p + TPB), acc1);
            p += n - 2 - i;
        }
        // ---- partial rows (row crosses the diagonal inside this strip) ----
        for (; i < iend; ++i) {
            const float xi = __ldg(x + i);
            float ca = 0.0f, cb = 0.0f;
            if (j_a > i) ca = __ldcs(p);
            if (j_b > i) cb = __ldcs(p + TPB);
            acc0 = fmaf(xi, ca, acc0);
            acc1 = fmaf(xi, cb, acc1);
            p += n - 2 - i;
        }

        sum += acc0 * __ldg(x + j_a) + acc1 * __ldg(x + j_b);

        u = Pjs + i;
        if (i == K) { Pjs += K; ++js; i = 0; }
    }

    // block reduction: warp shuffle -> smem -> warp 0 -> one atomic per block
    __shared__ float wsum[TPB / 32];
    float w = warp_sum(sum);
    if ((t & 31) == 0) wsum[t >> 5] = w;
    __syncthreads();
    if (t < 32) {
        float v = (t < TPB / 32) ? wsum[t] : 0.0f;
        v = warp_sum(v);
        if (t == 0) atomicAdd(out, v);
    }
}

extern "C" void kernel_launch(void* const* d_in, const int* in_sizes, int n_in,
                              void* d_out, int out_size) {
    const float* x = (const float*)d_in[0];
    const float* c = (const float*)d_in[1];
    float* out = (float*)d_out;
    const int n = in_sizes[0];   // 8192

    zero_out_kernel<<<1, 32>>>(out);
    ham_kernel<<<NBLOCKS, TPB>>>(x, c, out, n);
}